// round 5
// baseline (speedup 1.0000x reference)
#include <cuda_runtime.h>
#include <cuda_bf16.h>
#include <mma.h>
#include <math.h>
#include <cstdint>

using namespace nvcuda;

#define BATCH 4
#define SEQ 1024
#define DIM 1024
#define NHEADS 16
#define HDIM 64
#define MLP 4096
#define MTOT (BATCH*SEQ)        /* 4096 */
#define QKVW (5*NHEADS*HDIM)    /* 5120 */
#define ATTN_CLIP 100.0f
#define NORM_CLIP 1000.0f
#define EPSF 1e-6f

// ================= scratch =================
__device__ float g_qkv[MTOT*QKVW];                       // 80MB
__device__ float g_x2 [MTOT*DIM];                        // 16MB
__device__ __nv_bfloat16 g_hA[(size_t)MTOT*3*DIM];       // augmented A (h / o / h2): 25MB
__device__ __nv_bfloat16 g_fA[(size_t)MTOT*3*MLP];       // augmented f: 100MB
__device__ __nv_bfloat16 g_B [(size_t)QKVW*3*DIM];       // augmented weights: 31.5MB
__device__ float g_part[BATCH*128];
__device__ float g_nx[BATCH];
__device__ float g_lam;

// ================= cp.async =================
__device__ __forceinline__ uint32_t smem_u32(const void* p) {
    uint32_t a;
    asm("{ .reg .u64 t; cvta.to.shared.u64 t, %1; cvt.u32.u64 %0, t; }" : "=r"(a) : "l"(p));
    return a;
}
#define CP_ASYNC16(dst, src) \
    asm volatile("cp.async.cg.shared.global [%0], [%1], 16;" :: "r"(dst), "l"(src))
#define CP_COMMIT() asm volatile("cp.async.commit_group;" ::: "memory")
#define CP_WAIT(n)  asm volatile("cp.async.wait_group %0;" :: "n"(n) : "memory")

// ================= scalar kernels =================
__global__ void reduce_sq_kernel(const float* __restrict__ x) {
    const int b = blockIdx.y, blk = blockIdx.x;
    const int N = SEQ*DIM;
    const int per = N / 128;
    const float* p = x + (size_t)b*N + (size_t)blk*per;
    float s = 0.f;
    for (int i = threadIdx.x; i < per; i += 256) { float v = p[i]; s += v*v; }
    __shared__ float red[8];
    int lane = threadIdx.x & 31, w = threadIdx.x >> 5;
#pragma unroll
    for (int o = 16; o; o >>= 1) s += __shfl_down_sync(0xffffffffu, s, o);
    if (lane == 0) red[w] = s;
    __syncthreads();
    if (w == 0) {
        s = (lane < 8) ? red[lane] : 0.f;
#pragma unroll
        for (int o = 4; o; o >>= 1) s += __shfl_down_sync(0xffffffffu, s, o);
        if (lane == 0) g_part[b*128 + blk] = s;
    }
}

__global__ void compute_nx_kernel() {
    int b = threadIdx.x;
    if (b < BATCH) {
        float s = 0.f;
        for (int i = 0; i < 128; i++) s += g_part[b*128 + i];
        s = fminf(fmaxf(s, EPSF), NORM_CLIP);
        float gx = sqrtf(s);
        float nx = gx / (gx + EPSF);
        nx = fminf(fmaxf(nx, -NORM_CLIP), NORM_CLIP);
        g_nx[b] = nx;
    }
}

__global__ void compute_lam_kernel(const float* __restrict__ lq1, const float* __restrict__ lk1,
                                   const float* __restrict__ lq2, const float* __restrict__ lk2) {
    float s1 = 0.f, s2 = 0.f;
    for (int d = 0; d < HDIM; d++) { s1 += lq1[d]*lk1[d]; s2 += lq2[d]*lk2[d]; }
    s1 = fminf(fmaxf(s1, -10.f), 10.f);
    s2 = fminf(fmaxf(s2, -10.f), 10.f);
    float lam_init = 0.8f - 0.6f*expf(-0.0f);
    float lam = expf(s1) - expf(s2) + lam_init;
    g_lam = fminf(fmaxf(lam, 0.1f), 5.f);
}

// ================= GRN fused with augmented split =================
// out_aug[row][0:D)=hi, [D:2D)=lo, [2D:3D)=hi  of  gamma*(x*nx)+beta+x
__global__ void grn_split_kernel(const float* __restrict__ x, const float* __restrict__ gamma,
                                 const float* __restrict__ beta, __nv_bfloat16* __restrict__ Aaug) {
    int idx = blockIdx.x*blockDim.x + threadIdx.x;
    int e = idx * 4;
    int b = e >> 20;                 // / (SEQ*DIM)
    int row = e >> 10;               // / DIM
    int d = e & (DIM-1);
    float nx = g_nx[b];
    float4 xv = *(const float4*)(x + e);
    float4 gv = *(const float4*)(gamma + d);
    float4 bv = *(const float4*)(beta + d);
    float r0 = gv.x*(xv.x*nx) + bv.x + xv.x;
    float r1 = gv.y*(xv.y*nx) + bv.y + xv.y;
    float r2 = gv.z*(xv.z*nx) + bv.z + xv.z;
    float r3 = gv.w*(xv.w*nx) + bv.w + xv.w;
    __nv_bfloat16 h0 = __float2bfloat16(r0), h1 = __float2bfloat16(r1);
    __nv_bfloat16 h2 = __float2bfloat16(r2), h3 = __float2bfloat16(r3);
    __nv_bfloat16 l0 = __float2bfloat16(r0 - __bfloat162float(h0));
    __nv_bfloat16 l1 = __float2bfloat16(r1 - __bfloat162float(h1));
    __nv_bfloat16 l2 = __float2bfloat16(r2 - __bfloat162float(h2));
    __nv_bfloat16 l3 = __float2bfloat16(r3 - __bfloat162float(h3));
    __nv_bfloat162 hp0; hp0.x = h0; hp0.y = h1;
    __nv_bfloat162 hp1; hp1.x = h2; hp1.y = h3;
    __nv_bfloat162 lp0; lp0.x = l0; lp0.y = l1;
    __nv_bfloat162 lp1; lp1.x = l2; lp1.y = l3;
    __nv_bfloat16* dst = Aaug + (size_t)row*(3*DIM) + d;
    *(__nv_bfloat162*)(dst)            = hp0; *(__nv_bfloat162*)(dst + 2)          = hp1;
    *(__nv_bfloat162*)(dst + DIM)      = lp0; *(__nv_bfloat162*)(dst + DIM + 2)    = lp1;
    *(__nv_bfloat162*)(dst + 2*DIM)    = hp0; *(__nv_bfloat162*)(dst + 2*DIM + 2)  = hp1;
}

// ================= weight transpose + augmented split =================
// w[K][N] fp32 -> Baug[N][3K]: [0:K)=hi, [K:2K)=hi, [2K:3K)=lo
__global__ void transpose_split_aug(const float* __restrict__ w,
                                    __nv_bfloat16* __restrict__ Baug, int K, int N) {
    __shared__ float tile[32][33];
    int n0 = blockIdx.x * 32, k0 = blockIdx.y * 32;
    int tx = threadIdx.x, ty = threadIdx.y;   // 32 x 8
#pragma unroll
    for (int i = 0; i < 4; i++)
        tile[ty + i*8][tx] = w[(size_t)(k0 + ty + i*8)*N + n0 + tx];
    __syncthreads();
#pragma unroll
    for (int i = 0; i < 4; i++) {
        float v = tile[tx][ty + i*8];
        __nv_bfloat16 h = __float2bfloat16(v);
        __nv_bfloat16 l = __float2bfloat16(v - __bfloat162float(h));
        size_t o = (size_t)(n0 + ty + i*8)*(3*K) + k0 + tx;
        Baug[o] = h; Baug[o + K] = h; Baug[o + 2*K] = l;
    }
}

// ================= single-pass bf16 wmma GEMM over augmented K =================
// A: [M][KA] bf16, B: [N][KA] bf16, KA = 3K
// EPI: 0 = fp32 out; 2 = fp32 out + bias + residual; 3 = silu(+bias) -> augmented bf16 out [M][3N]
#define KC 32
#define LDA 40
#define TILE_ELEMS (128*LDA)          /* 5120 elems */
#define BUFE (2*TILE_ELEMS)           /* A+B per stage: 10240 elems = 20KB */
#define SLD 132
#define SMEM_WG (128*SLD*4)           /* 67584B stage > 2*BUFE*2 = 40960B */

template<int EPI>
__global__ __launch_bounds__(256, 2)
void wmma_gemm(const __nv_bfloat16* __restrict__ A, const __nv_bfloat16* __restrict__ B,
               void* __restrict__ Cv, int M, int N, int KA,
               const float* __restrict__ bias, const float* __restrict__ res) {
    extern __shared__ char smem_raw[];
    __nv_bfloat16* sm = (__nv_bfloat16*)smem_raw;
    const uint32_t sm_addr = smem_u32(sm);

    const int tid = threadIdx.x;
    const int wid = tid >> 5;
    const int row0 = blockIdx.y * 128;
    const int col0 = blockIdx.x * 128;
    const int wr = (wid >> 1) * 32;
    const int wc = (wid & 1) * 64;

    const __nv_bfloat16* Abase = A + (size_t)row0 * KA;
    const __nv_bfloat16* Bbase = B + (size_t)col0 * KA;

    auto issue_chunk = [&](int k0, int buf) {
        uint32_t dbase = sm_addr + (uint32_t)buf * (BUFE*2);
#pragma unroll
        for (int s = 0; s < 2; s++) {
            int idx = tid + s*256;
            int r = idx >> 2, cu = (idx & 3) * 8;
            CP_ASYNC16(dbase + (uint32_t)(r*LDA + cu)*2,
                       Abase + (size_t)r*KA + k0 + cu);
            CP_ASYNC16(dbase + (uint32_t)(TILE_ELEMS + r*LDA + cu)*2,
                       Bbase + (size_t)r*KA + k0 + cu);
        }
        CP_COMMIT();
    };

    wmma::fragment<wmma::accumulator, 16, 16, 16, float> acc[2][4];
#pragma unroll
    for (int i = 0; i < 2; i++)
#pragma unroll
        for (int j = 0; j < 4; j++) wmma::fill_fragment(acc[i][j], 0.f);

    const int nch = KA / KC;
    issue_chunk(0, 0);

    for (int ch = 0; ch < nch; ch++) {
        const int cur = ch & 1;
        if (ch + 1 < nch) { issue_chunk((ch+1)*KC, cur ^ 1); CP_WAIT(1); }
        else              { CP_WAIT(0); }
        __syncthreads();

        const __nv_bfloat16* tA = sm + cur*BUFE + wr*LDA;
        const __nv_bfloat16* tB = sm + cur*BUFE + TILE_ELEMS + wc*LDA;

#pragma unroll
        for (int ks = 0; ks < 2; ks++) {
            const int ko = ks * 16;
            wmma::fragment<wmma::matrix_a, 16, 16, 16, __nv_bfloat16, wmma::row_major> aF[2];
            wmma::fragment<wmma::matrix_b, 16, 16, 16, __nv_bfloat16, wmma::col_major> bF[4];
#pragma unroll
            for (int i = 0; i < 2; i++)
                wmma::load_matrix_sync(aF[i], tA + i*16*LDA + ko, LDA);
#pragma unroll
            for (int j = 0; j < 4; j++)
                wmma::load_matrix_sync(bF[j], tB + j*16*LDA + ko, LDA);
#pragma unroll
            for (int i = 0; i < 2; i++)
#pragma unroll
                for (int j = 0; j < 4; j++)
                    wmma::mma_sync(acc[i][j], aF[i], bF[j], acc[i][j]);
        }
        __syncthreads();
    }

    // epilogue via smem stage
    float* stage = (float*)smem_raw;
#pragma unroll
    for (int i = 0; i < 2; i++)
#pragma unroll
        for (int j = 0; j < 4; j++)
            wmma::store_matrix_sync(stage + (wr + i*16)*SLD + wc + j*16,
                                    acc[i][j], SLD, wmma::mem_row_major);
    __syncthreads();

    const int r = tid >> 1;
    const int c0 = (tid & 1) * 64;
    const int row = row0 + r;

    if (EPI == 3) {
        // silu(+bias) -> augmented bf16 [M][3N]: [c]=hi, [N+c]=lo, [2N+c]=hi
        __nv_bfloat16* C = (__nv_bfloat16*)Cv;
        __nv_bfloat16* dst = C + (size_t)row*(3*N) + col0 + c0;
#pragma unroll
        for (int j = 0; j < 32; j++) {
            float t0 = stage[r*SLD + c0 + j*2]     + bias[col0 + c0 + j*2];
            float t1 = stage[r*SLD + c0 + j*2 + 1] + bias[col0 + c0 + j*2 + 1];
            t0 = t0 / (1.f + __expf(-t0));
            t1 = t1 / (1.f + __expf(-t1));
            __nv_bfloat16 h0 = __float2bfloat16(t0), h1 = __float2bfloat16(t1);
            __nv_bfloat16 l0 = __float2bfloat16(t0 - __bfloat162float(h0));
            __nv_bfloat16 l1 = __float2bfloat16(t1 - __bfloat162float(h1));
            __nv_bfloat162 hp; hp.x = h0; hp.y = h1;
            __nv_bfloat162 lp; lp.x = l0; lp.y = l1;
            *(__nv_bfloat162*)(dst + j*2)         = hp;
            *(__nv_bfloat162*)(dst + N + j*2)     = lp;
            *(__nv_bfloat162*)(dst + 2*N + j*2)   = hp;
        }
    } else {
        float* C = (float*)Cv;
        size_t obase = (size_t)row*N + col0 + c0;
#pragma unroll
        for (int j = 0; j < 16; j++) {
            float4 v = *(float4*)(stage + r*SLD + c0 + j*4);
            float* vi = (float*)&v;
            float4 w;
            float* wi = (float*)&w;
#pragma unroll
            for (int q = 0; q < 4; q++) {
                float t = vi[q];
                if (EPI == 2) t += bias[col0 + c0 + j*4 + q] + res[obase + j*4 + q];
                wi[q] = t;
            }
            *(float4*)(C + obase + j*4) = w;
        }
    }
}

// ================= fused differential flash attention (aug-bf16 output) =================
#define PITCH 65
#define SMEM_ATTN (7 * 64 * PITCH * 4)

__global__ __launch_bounds__(256)
void diff_attn_kernel(const float* __restrict__ qkv, __nv_bfloat16* __restrict__ o_aug) {
    extern __shared__ float sm[];
    float* q1s = sm;
    float* q2s = q1s + 64*PITCH;
    float* k1s = q2s + 64*PITCH;
    float* k2s = k1s + 64*PITCH;
    float* vs  = k2s + 64*PITCH;
    float* s1  = vs  + 64*PITCH;
    float* s2  = s1  + 64*PITCH;

    const int tid = threadIdx.x;
    const int qt = blockIdx.x, h = blockIdx.y, b = blockIdx.z;
    const int q0 = qt * 64;
    const float scale = 0.125f;
    const float lam = g_lam;

    const size_t base = ((size_t)b*SEQ)*QKVW + (size_t)h*HDIM;

    for (int idx = tid; idx < 64*64; idx += 256) {
        int r = idx >> 6, c = idx & 63;
        size_t g = base + (size_t)(q0 + r)*QKVW + c;
        q1s[r*PITCH + c] = qkv[g + 0*NHEADS*HDIM];
        q2s[r*PITCH + c] = qkv[g + 1*NHEADS*HDIM];
    }

    const int r  = tid >> 2;
    const int kg = (tid & 3) * 16;
    const int dbase = kg;
    float m1 = -1e30f, l1 = 0.f, m2 = -1e30f, l2 = 0.f;
    float o1[16], o2[16];
#pragma unroll
    for (int j = 0; j < 16; j++) { o1[j] = 0.f; o2[j] = 0.f; }

    const int sr0 = (tid >> 4) * 4;
    const int sk0 = (tid & 15) * 4;

    __syncthreads();

    for (int kt = 0; kt < 16; ++kt) {
        const int k0i = kt * 64;
        for (int idx = tid; idx < 64*64; idx += 256) {
            int rr = idx >> 6, c = idx & 63;
            size_t g = base + (size_t)(k0i + rr)*QKVW + c;
            k1s[rr*PITCH + c] = qkv[g + 2*NHEADS*HDIM];
            k2s[rr*PITCH + c] = qkv[g + 3*NHEADS*HDIM];
            vs [rr*PITCH + c] = qkv[g + 4*NHEADS*HDIM];
        }
        __syncthreads();

        {
            float acc1[4][4], acc2[4][4];
#pragma unroll
            for (int i = 0; i < 4; i++)
#pragma unroll
                for (int j = 0; j < 4; j++) { acc1[i][j] = 0.f; acc2[i][j] = 0.f; }
            for (int d = 0; d < 64; ++d) {
                float qa1[4], qa2[4], kb1[4], kb2[4];
#pragma unroll
                for (int i = 0; i < 4; i++) {
                    qa1[i] = q1s[(sr0+i)*PITCH + d];
                    qa2[i] = q2s[(sr0+i)*PITCH + d];
                    kb1[i] = k1s[(sk0+i)*PITCH + d];
                    kb2[i] = k2s[(sk0+i)*PITCH + d];
                }
#pragma unroll
                for (int i = 0; i < 4; i++)
#pragma unroll
                    for (int j = 0; j < 4; j++) {
                        acc1[i][j] += qa1[i]*kb1[j];
                        acc2[i][j] += qa2[i]*kb2[j];
                    }
            }
#pragma unroll
            for (int i = 0; i < 4; i++)
#pragma unroll
                for (int j = 0; j < 4; j++) {
                    s1[(sr0+i)*PITCH + sk0+j] =
                        fminf(fmaxf(acc1[i][j]*scale, -ATTN_CLIP), ATTN_CLIP);
                    s2[(sr0+i)*PITCH + sk0+j] =
                        fminf(fmaxf(acc2[i][j]*scale, -ATTN_CLIP), ATTN_CLIP);
                }
        }
        __syncthreads();

        {
            float tm1 = -1e30f, tm2 = -1e30f;
#pragma unroll
            for (int i = 0; i < 16; i++) {
                tm1 = fmaxf(tm1, s1[r*PITCH + kg + i]);
                tm2 = fmaxf(tm2, s2[r*PITCH + kg + i]);
            }
            tm1 = fmaxf(tm1, __shfl_xor_sync(0xffffffffu, tm1, 1));
            tm1 = fmaxf(tm1, __shfl_xor_sync(0xffffffffu, tm1, 2));
            tm2 = fmaxf(tm2, __shfl_xor_sync(0xffffffffu, tm2, 1));
            tm2 = fmaxf(tm2, __shfl_xor_sync(0xffffffffu, tm2, 2));
            float nm1 = fmaxf(m1, tm1), nm2 = fmaxf(m2, tm2);
            float ts1 = 0.f, ts2 = 0.f;
#pragma unroll
            for (int i = 0; i < 16; i++) {
                float p1 = __expf(s1[r*PITCH + kg + i] - nm1);
                s1[r*PITCH + kg + i] = p1; ts1 += p1;
                float p2 = __expf(s2[r*PITCH + kg + i] - nm2);
                s2[r*PITCH + kg + i] = p2; ts2 += p2;
            }
            ts1 += __shfl_xor_sync(0xffffffffu, ts1, 1);
            ts1 += __shfl_xor_sync(0xffffffffu, ts1, 2);
            ts2 += __shfl_xor_sync(0xffffffffu, ts2, 1);
            ts2 += __shfl_xor_sync(0xffffffffu, ts2, 2);
            float c1 = __expf(m1 - nm1), c2 = __expf(m2 - nm2);
            l1 = l1*c1 + ts1;  l2 = l2*c2 + ts2;
#pragma unroll
            for (int j = 0; j < 16; j++) { o1[j] *= c1; o2[j] *= c2; }
            m1 = nm1; m2 = nm2;
        }
        __syncwarp();

#pragma unroll 4
        for (int kk = 0; kk < 64; ++kk) {
            float p1 = s1[r*PITCH + kk], p2 = s2[r*PITCH + kk];
            const float* vrow = &vs[kk*PITCH + dbase];
#pragma unroll
            for (int j = 0; j < 16; j++) {
                float vv = vrow[j];
                o1[j] += p1*vv;
                o2[j] += p2*vv;
            }
        }
        __syncthreads();
    }

    const float inv1 = 1.f / (l1 + EPSF);
    const float inv2 = 1.f / (l2 + EPSF);
    const int orow = b*SEQ + q0 + r;
    const int ocol = h*HDIM + dbase;
    __nv_bfloat16* dst = o_aug + (size_t)orow*(3*DIM) + ocol;
#pragma unroll
    for (int j = 0; j < 16; j += 2) {
        float v0 = o1[j]*inv1   - lam*(o2[j]*inv2);
        float v1 = o1[j+1]*inv1 - lam*(o2[j+1]*inv2);
        __nv_bfloat16 h0 = __float2bfloat16(v0), h1 = __float2bfloat16(v1);
        __nv_bfloat16 l0 = __float2bfloat16(v0 - __bfloat162float(h0));
        __nv_bfloat16 l1b = __float2bfloat16(v1 - __bfloat162float(h1));
        __nv_bfloat162 hp; hp.x = h0; hp.y = h1;
        __nv_bfloat162 lp; lp.x = l0; lp.y = l1b;
        *(__nv_bfloat162*)(dst + j)          = hp;
        *(__nv_bfloat162*)(dst + DIM + j)    = lp;
        *(__nv_bfloat162*)(dst + 2*DIM + j)  = hp;
    }
}

// ================= launch =================
extern "C" void kernel_launch(void* const* d_in, const int* in_sizes, int n_in,
                              void* d_out, int out_size) {
    const float* x      = (const float*)d_in[0];
    const float* w_qkv  = (const float*)d_in[1];
    const float* lq1    = (const float*)d_in[2];
    const float* lk1    = (const float*)d_in[3];
    const float* lq2    = (const float*)d_in[4];
    const float* lk2    = (const float*)d_in[5];
    const float* w_proj = (const float*)d_in[6];
    const float* b_proj = (const float*)d_in[7];
    const float* gamma1 = (const float*)d_in[8];
    const float* beta1  = (const float*)d_in[9];
    const float* gamma2 = (const float*)d_in[10];
    const float* beta2  = (const float*)d_in[11];
    const float* w1     = (const float*)d_in[12];
    const float* b1     = (const float*)d_in[13];
    const float* w2     = (const float*)d_in[14];
    const float* b2     = (const float*)d_in[15];
    float* out = (float*)d_out;

    float *p_qkv, *p_x2;
    __nv_bfloat16 *p_hA, *p_fA, *p_B;
    cudaGetSymbolAddress((void**)&p_qkv, g_qkv);
    cudaGetSymbolAddress((void**)&p_x2,  g_x2);
    cudaGetSymbolAddress((void**)&p_hA,  g_hA);
    cudaGetSymbolAddress((void**)&p_fA,  g_fA);
    cudaGetSymbolAddress((void**)&p_B,   g_B);

    cudaFuncSetAttribute(diff_attn_kernel,
                         cudaFuncAttributeMaxDynamicSharedMemorySize, SMEM_ATTN);
    cudaFuncSetAttribute(wmma_gemm<0>, cudaFuncAttributeMaxDynamicSharedMemorySize, SMEM_WG);
    cudaFuncSetAttribute(wmma_gemm<2>, cudaFuncAttributeMaxDynamicSharedMemorySize, SMEM_WG);
    cudaFuncSetAttribute(wmma_gemm<3>, cudaFuncAttributeMaxDynamicSharedMemorySize, SMEM_WG);

    // scalars
    reduce_sq_kernel<<<dim3(128, BATCH), 256>>>(x);
    compute_nx_kernel<<<1, 32>>>();
    compute_lam_kernel<<<1, 1>>>(lq1, lk1, lq2, lk2);

    // GRN1 fused split -> hA (aug)
    grn_split_kernel<<<(MTOT*DIM)/4/256, 256>>>(x, gamma1, beta1, p_hA);

    // QKV GEMM: hA(4096 x 3072aug) @ w_qkv_aug -> qkv fp32
    transpose_split_aug<<<dim3(QKVW/32, DIM/32), dim3(32, 8)>>>(w_qkv, p_B, DIM, QKVW);
    wmma_gemm<0><<<dim3(QKVW/128, MTOT/128), 256, SMEM_WG>>>(
        p_hA, p_B, p_qkv, MTOT, QKVW, 3*DIM, nullptr, nullptr);

    // differential flash attention -> o_aug (into hA)
    diff_attn_kernel<<<dim3(SEQ/64, NHEADS, BATCH), 256, SMEM_ATTN>>>(p_qkv, p_hA);

    // proj + bias + residual(x) -> x2 fp32
    transpose_split_aug<<<dim3(DIM/32, DIM/32), dim3(32, 8)>>>(w_proj, p_B, DIM, DIM);
    wmma_gemm<2><<<dim3(DIM/128, MTOT/128), 256, SMEM_WG>>>(
        p_hA, p_B, p_x2, MTOT, DIM, 3*DIM, b_proj, x);

    // GRN2 fused split -> hA (aug)
    reduce_sq_kernel<<<dim3(128, BATCH), 256>>>(p_x2);
    compute_nx_kernel<<<1, 32>>>();
    grn_split_kernel<<<(MTOT*DIM)/4/256, 256>>>(p_x2, gamma2, beta2, p_hA);

    // FFN1: silu(hA @ w1 + b1) -> fA (aug bf16 direct)
    transpose_split_aug<<<dim3(MLP/32, DIM/32), dim3(32, 8)>>>(w1, p_B, DIM, MLP);
    wmma_gemm<3><<<dim3(MLP/128, MTOT/128), 256, SMEM_WG>>>(
        p_hA, p_B, p_fA, MTOT, MLP, 3*DIM, b1, nullptr);

    // FFN2: fA(4096 x 12288aug) @ w2_aug + b2 + residual(x2) -> out
    transpose_split_aug<<<dim3(DIM/32, MLP/32), dim3(32, 8)>>>(w2, p_B, MLP, DIM);
    wmma_gemm<2><<<dim3(DIM/128, MTOT/128), 256, SMEM_WG>>>(
        p_fA, p_B, out, MTOT, DIM, 3*MLP, b2, p_x2);
}

// round 6
// speedup vs baseline: 2.5662x; 2.5662x over previous
#include <cuda_runtime.h>
#include <cuda_bf16.h>
#include <mma.h>
#include <math.h>
#include <cstdint>

using namespace nvcuda;

#define BATCH 4
#define SEQ 1024
#define DIM 1024
#define NHEADS 16
#define HDIM 64
#define MLP 4096
#define MTOT (BATCH*SEQ)        /* 4096 */
#define QKVW (5*NHEADS*HDIM)    /* 5120 */
#define ATTN_CLIP 100.0f
#define NORM_CLIP 1000.0f
#define EPSF 1e-6f

// ================= scratch =================
__device__ float g_h  [MTOT*DIM];
__device__ float g_qkv[MTOT*QKVW];
__device__ float g_o  [MTOT*DIM];
__device__ float g_x2 [MTOT*DIM];
__device__ float g_h2 [MTOT*DIM];
__device__ float g_f  [(size_t)MTOT*MLP];
__device__ __nv_bfloat16 g_ahi[(size_t)MTOT*MLP];
__device__ __nv_bfloat16 g_alo[(size_t)MTOT*MLP];
__device__ __nv_bfloat16 g_bhi[(size_t)QKVW*DIM];
__device__ __nv_bfloat16 g_blo[(size_t)QKVW*DIM];
__device__ float g_part[BATCH*128];
__device__ float g_nx[BATCH];
__device__ float g_lam;

// ================= cp.async =================
__device__ __forceinline__ uint32_t smem_u32(const void* p) {
    uint32_t a;
    asm("{ .reg .u64 t; cvta.to.shared.u64 t, %1; cvt.u32.u64 %0, t; }" : "=r"(a) : "l"(p));
    return a;
}
#define CP_ASYNC16(dst, src) \
    asm volatile("cp.async.cg.shared.global [%0], [%1], 16;" :: "r"(dst), "l"(src))
#define CP_COMMIT() asm volatile("cp.async.commit_group;" ::: "memory")
#define CP_WAIT(n)  asm volatile("cp.async.wait_group %0;" :: "n"(n) : "memory")

// ================= mma.sync m16n8k16 bf16 =================
#define MMA_BF16(d, a, b) \
    asm volatile("mma.sync.aligned.m16n8k16.row.col.f32.bf16.bf16.f32 " \
        "{%0,%1,%2,%3}, {%4,%5,%6,%7}, {%8,%9}, {%0,%1,%2,%3};" \
        : "+f"((d)[0]), "+f"((d)[1]), "+f"((d)[2]), "+f"((d)[3]) \
        : "r"((a)[0]), "r"((a)[1]), "r"((a)[2]), "r"((a)[3]), \
          "r"((b)[0]), "r"((b)[1]))

__device__ __forceinline__ uint32_t pk2(float x, float y) {
    __nv_bfloat162 t = __floats2bfloat162_rn(x, y);
    return *(uint32_t*)&t;
}
__device__ __forceinline__ uint32_t pk2lo(float x, float y, uint32_t hipk) {
    __nv_bfloat162 hp = *(__nv_bfloat162*)&hipk;
    return pk2(x - __bfloat162float(hp.x), y - __bfloat162float(hp.y));
}

// ================= scalar / GRN kernels =================
__global__ void reduce_sq_kernel(const float* __restrict__ x) {
    const int b = blockIdx.y, blk = blockIdx.x;
    const int N = SEQ*DIM;
    const int per = N / 128;
    const float* p = x + (size_t)b*N + (size_t)blk*per;
    float s = 0.f;
    for (int i = threadIdx.x; i < per; i += 256) { float v = p[i]; s += v*v; }
    __shared__ float red[8];
    int lane = threadIdx.x & 31, w = threadIdx.x >> 5;
#pragma unroll
    for (int o = 16; o; o >>= 1) s += __shfl_down_sync(0xffffffffu, s, o);
    if (lane == 0) red[w] = s;
    __syncthreads();
    if (w == 0) {
        s = (lane < 8) ? red[lane] : 0.f;
#pragma unroll
        for (int o = 4; o; o >>= 1) s += __shfl_down_sync(0xffffffffu, s, o);
        if (lane == 0) g_part[b*128 + blk] = s;
    }
}

__global__ void compute_nx_kernel() {
    int b = threadIdx.x;
    if (b < BATCH) {
        float s = 0.f;
        for (int i = 0; i < 128; i++) s += g_part[b*128 + i];
        s = fminf(fmaxf(s, EPSF), NORM_CLIP);
        float gx = sqrtf(s);
        float nx = gx / (gx + EPSF);
        nx = fminf(fmaxf(nx, -NORM_CLIP), NORM_CLIP);
        g_nx[b] = nx;
    }
}

__global__ void compute_lam_kernel(const float* __restrict__ lq1, const float* __restrict__ lk1,
                                   const float* __restrict__ lq2, const float* __restrict__ lk2) {
    float s1 = 0.f, s2 = 0.f;
    for (int d = 0; d < HDIM; d++) { s1 += lq1[d]*lk1[d]; s2 += lq2[d]*lk2[d]; }
    s1 = fminf(fmaxf(s1, -10.f), 10.f);
    s2 = fminf(fmaxf(s2, -10.f), 10.f);
    float lam_init = 0.8f - 0.6f*expf(-0.0f);
    float lam = expf(s1) - expf(s2) + lam_init;
    g_lam = fminf(fmaxf(lam, 0.1f), 5.f);
}

__global__ void grn_kernel(const float* __restrict__ x, const float* __restrict__ gamma,
                           const float* __restrict__ beta, float* __restrict__ out) {
    int idx = blockIdx.x*blockDim.x + threadIdx.x;
    int e = idx * 4;
    int b = e / (SEQ*DIM);
    int d = e % DIM;
    float nx = g_nx[b];
    float4 xv = *(const float4*)(x + e);
    float4 gv = *(const float4*)(gamma + d);
    float4 bv = *(const float4*)(beta + d);
    float4 r;
    r.x = gv.x*(xv.x*nx) + bv.x + xv.x;
    r.y = gv.y*(xv.y*nx) + bv.y + xv.y;
    r.z = gv.z*(xv.z*nx) + bv.z + xv.z;
    r.w = gv.w*(xv.w*nx) + bv.w + xv.w;
    *(float4*)(out + e) = r;
}

// ================= fp32 -> bf16 hi/lo split =================
__global__ void split_kernel(const float* __restrict__ x,
                             __nv_bfloat16* __restrict__ hi,
                             __nv_bfloat16* __restrict__ lo) {
    int idx = blockIdx.x*blockDim.x + threadIdx.x;
    int e = idx * 4;
    float4 v = *(const float4*)(x + e);
    __nv_bfloat16 h0 = __float2bfloat16(v.x), h1 = __float2bfloat16(v.y);
    __nv_bfloat16 h2 = __float2bfloat16(v.z), h3 = __float2bfloat16(v.w);
    __nv_bfloat16 l0 = __float2bfloat16(v.x - __bfloat162float(h0));
    __nv_bfloat16 l1 = __float2bfloat16(v.y - __bfloat162float(h1));
    __nv_bfloat16 l2 = __float2bfloat16(v.z - __bfloat162float(h2));
    __nv_bfloat16 l3 = __float2bfloat16(v.w - __bfloat162float(h3));
    __nv_bfloat162 hp0; hp0.x = h0; hp0.y = h1;
    __nv_bfloat162 hp1; hp1.x = h2; hp1.y = h3;
    __nv_bfloat162 lp0; lp0.x = l0; lp0.y = l1;
    __nv_bfloat162 lp1; lp1.x = l2; lp1.y = l3;
    *(__nv_bfloat162*)(hi + e) = hp0; *(__nv_bfloat162*)(hi + e + 2) = hp1;
    *(__nv_bfloat162*)(lo + e) = lp0; *(__nv_bfloat162*)(lo + e + 2) = lp1;
}

// ================= weight transpose + split =================
__global__ void transpose_split_kernel(const float* __restrict__ w,
                                       __nv_bfloat16* __restrict__ thi,
                                       __nv_bfloat16* __restrict__ tlo,
                                       int K, int N) {
    __shared__ float tile[32][33];
    int n0 = blockIdx.x * 32, k0 = blockIdx.y * 32;
    int tx = threadIdx.x, ty = threadIdx.y;
#pragma unroll
    for (int i = 0; i < 4; i++)
        tile[ty + i*8][tx] = w[(size_t)(k0 + ty + i*8)*N + n0 + tx];
    __syncthreads();
#pragma unroll
    for (int i = 0; i < 4; i++) {
        float v = tile[tx][ty + i*8];
        __nv_bfloat16 h = __float2bfloat16(v);
        __nv_bfloat16 l = __float2bfloat16(v - __bfloat162float(h));
        size_t o = (size_t)(n0 + ty + i*8)*K + k0 + tx;
        thi[o] = h; tlo[o] = l;
    }
}

// ================= wmma bf16-split GEMM (round-4 verbatim) =================
#define KC 32
#define LDA 40
#define TILE_ELEMS (128*LDA)
#define BUF_ELEMS (4*TILE_ELEMS)
#define SMEM_WG (2*BUF_ELEMS*2)
#define SLD 132

template<int EPI>
__global__ __launch_bounds__(256, 2)
void wmma_gemm(const __nv_bfloat16* __restrict__ Ahi, const __nv_bfloat16* __restrict__ Alo,
               const __nv_bfloat16* __restrict__ Bhi, const __nv_bfloat16* __restrict__ Blo,
               float* __restrict__ C, int M, int N, int K,
               const float* __restrict__ bias, const float* __restrict__ res) {
    extern __shared__ char smem_raw[];
    __nv_bfloat16* sm = (__nv_bfloat16*)smem_raw;
    const uint32_t sm_addr = smem_u32(sm);

    const int tid = threadIdx.x;
    const int wid = tid >> 5;
    const int row0 = blockIdx.y * 128;
    const int col0 = blockIdx.x * 128;
    const int wr = (wid >> 1) * 32;
    const int wc = (wid & 1) * 64;

    const __nv_bfloat16* gsrc[4] = {
        Ahi + (size_t)row0*K, Alo + (size_t)row0*K,
        Bhi + (size_t)col0*K, Blo + (size_t)col0*K };

    int u_arr[8], u_row[8], u_col[8];
#pragma unroll
    for (int i = 0; i < 8; i++) {
        int idx = tid + i*256;
        u_arr[i] = idx >> 9;
        int rem = idx & 511;
        u_row[i] = rem >> 2;
        u_col[i] = (rem & 3) * 8;
    }

    auto issue_chunk = [&](int k0, int buf) {
        uint32_t dbase = sm_addr + (uint32_t)buf * (BUF_ELEMS*2);
#pragma unroll
        for (int i = 0; i < 8; i++) {
            const __nv_bfloat16* src = gsrc[u_arr[i]] + (size_t)u_row[i]*K + k0 + u_col[i];
            uint32_t dst = dbase + (uint32_t)(u_arr[i]*TILE_ELEMS + u_row[i]*LDA + u_col[i]) * 2;
            CP_ASYNC16(dst, src);
        }
        CP_COMMIT();
    };

    wmma::fragment<wmma::accumulator, 16, 16, 16, float> acc[2][4];
#pragma unroll
    for (int i = 0; i < 2; i++)
#pragma unroll
        for (int j = 0; j < 4; j++) wmma::fill_fragment(acc[i][j], 0.f);

    const int nch = K / KC;
    issue_chunk(0, 0);

    for (int ch = 0; ch < nch; ch++) {
        const int cur = ch & 1;
        if (ch + 1 < nch) { issue_chunk((ch+1)*KC, cur ^ 1); CP_WAIT(1); }
        else              { CP_WAIT(0); }
        __syncthreads();

        const __nv_bfloat16* b0 = sm + cur * BUF_ELEMS;
        const __nv_bfloat16* tAhi = b0 + 0*TILE_ELEMS + wr*LDA;
        const __nv_bfloat16* tAlo = b0 + 1*TILE_ELEMS + wr*LDA;
        const __nv_bfloat16* tBhi = b0 + 2*TILE_ELEMS + wc*LDA;
        const __nv_bfloat16* tBlo = b0 + 3*TILE_ELEMS + wc*LDA;

#pragma unroll
        for (int ks = 0; ks < 2; ks++) {
            wmma::fragment<wmma::matrix_a, 16, 16, 16, __nv_bfloat16, wmma::row_major> aH[2], aL[2];
            wmma::fragment<wmma::matrix_b, 16, 16, 16, __nv_bfloat16, wmma::col_major> bF[4];
            const int ko = ks * 16;
#pragma unroll
            for (int i = 0; i < 2; i++)
                wmma::load_matrix_sync(aH[i], tAhi + i*16*LDA + ko, LDA);
#pragma unroll
            for (int j = 0; j < 4; j++)
                wmma::load_matrix_sync(bF[j], tBhi + j*16*LDA + ko, LDA);
#pragma unroll
            for (int i = 0; i < 2; i++)
#pragma unroll
                for (int j = 0; j < 4; j++)
                    wmma::mma_sync(acc[i][j], aH[i], bF[j], acc[i][j]);
#pragma unroll
            for (int i = 0; i < 2; i++)
                wmma::load_matrix_sync(aL[i], tAlo + i*16*LDA + ko, LDA);
#pragma unroll
            for (int i = 0; i < 2; i++)
#pragma unroll
                for (int j = 0; j < 4; j++)
                    wmma::mma_sync(acc[i][j], aL[i], bF[j], acc[i][j]);
#pragma unroll
            for (int j = 0; j < 4; j++)
                wmma::load_matrix_sync(bF[j], tBlo + j*16*LDA + ko, LDA);
#pragma unroll
            for (int i = 0; i < 2; i++)
#pragma unroll
                for (int j = 0; j < 4; j++)
                    wmma::mma_sync(acc[i][j], aH[i], bF[j], acc[i][j]);
        }
        __syncthreads();
    }

    float* stage = (float*)smem_raw;
#pragma unroll
    for (int i = 0; i < 2; i++)
#pragma unroll
        for (int j = 0; j < 4; j++)
            wmma::store_matrix_sync(stage + (wr + i*16)*SLD + wc + j*16,
                                    acc[i][j], SLD, wmma::mem_row_major);
    __syncthreads();

    const int r = tid >> 1;
    const int c0 = (tid & 1) * 64;
    const int row = row0 + r;
    size_t obase = (size_t)row*N + col0 + c0;
#pragma unroll
    for (int j = 0; j < 16; j++) {
        float4 v = *(float4*)(stage + r*SLD + c0 + j*4);
        float4 w;
        float* vi = (float*)&v; float* wi = (float*)&w;
#pragma unroll
        for (int q = 0; q < 4; q++) {
            float t = vi[q];
            if (EPI >= 1) t += bias[col0 + c0 + j*4 + q];
            if (EPI == 3) t = t / (1.f + __expf(-t));
            if (EPI == 2) t += res[obase + j*4 + q];
            wi[q] = t;
        }
        *(float4*)(C + obase + j*4) = w;
    }
}

// ================= tensor-core differential flash attention =================
// 128 threads (4 warps), q-tile 64 (16 rows/warp), k-tile 64, hd 64.
// Smem tiles bf16 with pitch 72 elems (conflict-free fragment access).
#define AP 72
#define TQ1H 0
#define TQ1L 4608
#define TQ2H 9216
#define TQ2L 13824
#define TK1H 18432
#define TK1L 23040
#define TK2H 27648
#define TK2L 32256
#define TVH  36864
#define TVL  41472
#define SMEM_ATT (46080*2)

__device__ __forceinline__ void softmax_upd(float sc[8][4], float m[2], float l[2],
                                            float oc[8][4]) {
    float t0 = -1e30f, t1 = -1e30f;
#pragma unroll
    for (int nb = 0; nb < 8; nb++) {
        t0 = fmaxf(t0, fmaxf(sc[nb][0], sc[nb][1]));
        t1 = fmaxf(t1, fmaxf(sc[nb][2], sc[nb][3]));
    }
    t0 = fmaxf(t0, __shfl_xor_sync(0xffffffffu, t0, 1));
    t0 = fmaxf(t0, __shfl_xor_sync(0xffffffffu, t0, 2));
    t1 = fmaxf(t1, __shfl_xor_sync(0xffffffffu, t1, 1));
    t1 = fmaxf(t1, __shfl_xor_sync(0xffffffffu, t1, 2));
    float nm0 = fmaxf(m[0], t0), nm1 = fmaxf(m[1], t1);
    float c0 = __expf(m[0] - nm0), c1 = __expf(m[1] - nm1);
    float s0 = 0.f, s1 = 0.f;
#pragma unroll
    for (int nb = 0; nb < 8; nb++) {
        float p0 = __expf(sc[nb][0] - nm0); sc[nb][0] = p0; s0 += p0;
        float p1 = __expf(sc[nb][1] - nm0); sc[nb][1] = p1; s0 += p1;
        float p2 = __expf(sc[nb][2] - nm1); sc[nb][2] = p2; s1 += p2;
        float p3 = __expf(sc[nb][3] - nm1); sc[nb][3] = p3; s1 += p3;
    }
    s0 += __shfl_xor_sync(0xffffffffu, s0, 1);
    s0 += __shfl_xor_sync(0xffffffffu, s0, 2);
    s1 += __shfl_xor_sync(0xffffffffu, s1, 1);
    s1 += __shfl_xor_sync(0xffffffffu, s1, 2);
    l[0] = l[0]*c0 + s0;  l[1] = l[1]*c1 + s1;
#pragma unroll
    for (int db = 0; db < 8; db++) {
        oc[db][0] *= c0; oc[db][1] *= c0;
        oc[db][2] *= c1; oc[db][3] *= c1;
    }
    m[0] = nm0; m[1] = nm1;
}

__global__ __launch_bounds__(128)
void diff_attn_mma(const float* __restrict__ qkv, float* __restrict__ o) {
    extern __shared__ __nv_bfloat16 sb[];
    const int tid = threadIdx.x;
    const int wid = tid >> 5, lane = tid & 31;
    const int g4 = lane >> 2, t4 = lane & 3;
    const int qt = blockIdx.x, h = blockIdx.y, b = blockIdx.z;
    const int q0 = qt * 64;
    const float lam = g_lam;
    const size_t base = ((size_t)b*SEQ)*QKVW + (size_t)h*HDIM;

    // load + split Q tiles (both streams)
    for (int i = tid; i < 64*64; i += 128) {
        int r = i >> 6, c = i & 63;
        size_t g = base + (size_t)(q0 + r)*QKVW + c;
        float v1 = qkv[g];
        float v2 = qkv[g + 1024];
        __nv_bfloat16 h1 = __float2bfloat16(v1);
        __nv_bfloat16 h2 = __float2bfloat16(v2);
        sb[TQ1H + r*AP + c] = h1;
        sb[TQ1L + r*AP + c] = __float2bfloat16(v1 - __bfloat162float(h1));
        sb[TQ2H + r*AP + c] = h2;
        sb[TQ2L + r*AP + c] = __float2bfloat16(v2 - __bfloat162float(h2));
    }

    float oc1[8][4], oc2[8][4];
#pragma unroll
    for (int i = 0; i < 8; i++)
#pragma unroll
        for (int j = 0; j < 4; j++) { oc1[i][j] = 0.f; oc2[i][j] = 0.f; }
    float m1[2] = {-1e30f, -1e30f}, l1[2] = {0.f, 0.f};
    float m2[2] = {-1e30f, -1e30f}, l2[2] = {0.f, 0.f};

    for (int kt = 0; kt < 16; kt++) {
        __syncthreads();    // Q/K/V smem writers vs readers of previous iter
        const int k0 = kt * 64;
        for (int i = tid; i < 64*64; i += 128) {
            int r = i >> 6, c = i & 63;
            size_t g = base + (size_t)(k0 + r)*QKVW + c;
            float vk1 = qkv[g + 2048];
            float vk2 = qkv[g + 3072];
            float vv  = qkv[g + 4096];
            __nv_bfloat16 hk1 = __float2bfloat16(vk1);
            __nv_bfloat16 hk2 = __float2bfloat16(vk2);
            __nv_bfloat16 hv  = __float2bfloat16(vv);
            sb[TK1H + r*AP + c] = hk1;
            sb[TK1L + r*AP + c] = __float2bfloat16(vk1 - __bfloat162float(hk1));
            sb[TK2H + r*AP + c] = hk2;
            sb[TK2L + r*AP + c] = __float2bfloat16(vk2 - __bfloat162float(hk2));
            sb[TVH + c*AP + r]  = hv;                    // transposed: [d][kk]
            sb[TVL + c*AP + r]  = __float2bfloat16(vv - __bfloat162float(hv));
        }
        __syncthreads();

        // ---- S = Q K^T (3-pass split, both streams) ----
        float sc1[8][4], sc2[8][4];
#pragma unroll
        for (int i = 0; i < 8; i++)
#pragma unroll
            for (int j = 0; j < 4; j++) { sc1[i][j] = 0.f; sc2[i][j] = 0.f; }

#pragma unroll
        for (int dc = 0; dc < 4; dc++) {
            const int ar = wid*16 + g4;
            const int ac = dc*16 + t4*2;
            uint32_t a1h[4], a1l[4], a2h[4], a2l[4];
            a1h[0] = *(const uint32_t*)&sb[TQ1H + ar*AP + ac];
            a1h[1] = *(const uint32_t*)&sb[TQ1H + (ar+8)*AP + ac];
            a1h[2] = *(const uint32_t*)&sb[TQ1H + ar*AP + ac + 8];
            a1h[3] = *(const uint32_t*)&sb[TQ1H + (ar+8)*AP + ac + 8];
            a1l[0] = *(const uint32_t*)&sb[TQ1L + ar*AP + ac];
            a1l[1] = *(const uint32_t*)&sb[TQ1L + (ar+8)*AP + ac];
            a1l[2] = *(const uint32_t*)&sb[TQ1L + ar*AP + ac + 8];
            a1l[3] = *(const uint32_t*)&sb[TQ1L + (ar+8)*AP + ac + 8];
            a2h[0] = *(const uint32_t*)&sb[TQ2H + ar*AP + ac];
            a2h[1] = *(const uint32_t*)&sb[TQ2H + (ar+8)*AP + ac];
            a2h[2] = *(const uint32_t*)&sb[TQ2H + ar*AP + ac + 8];
            a2h[3] = *(const uint32_t*)&sb[TQ2H + (ar+8)*AP + ac + 8];
            a2l[0] = *(const uint32_t*)&sb[TQ2L + ar*AP + ac];
            a2l[1] = *(const uint32_t*)&sb[TQ2L + (ar+8)*AP + ac];
            a2l[2] = *(const uint32_t*)&sb[TQ2L + ar*AP + ac + 8];
            a2l[3] = *(const uint32_t*)&sb[TQ2L + (ar+8)*AP + ac + 8];
#pragma unroll
            for (int nb = 0; nb < 8; nb++) {
                const int bo = (nb*8 + g4)*AP + dc*16 + t4*2;
                uint32_t b1h[2], b1l[2], b2h[2], b2l[2];
                b1h[0] = *(const uint32_t*)&sb[TK1H + bo];
                b1h[1] = *(const uint32_t*)&sb[TK1H + bo + 8];
                b1l[0] = *(const uint32_t*)&sb[TK1L + bo];
                b1l[1] = *(const uint32_t*)&sb[TK1L + bo + 8];
                b2h[0] = *(const uint32_t*)&sb[TK2H + bo];
                b2h[1] = *(const uint32_t*)&sb[TK2H + bo + 8];
                b2l[0] = *(const uint32_t*)&sb[TK2L + bo];
                b2l[1] = *(const uint32_t*)&sb[TK2L + bo + 8];
                MMA_BF16(sc1[nb], a1h, b1h);
                MMA_BF16(sc1[nb], a1l, b1h);
                MMA_BF16(sc1[nb], a1h, b1l);
                MMA_BF16(sc2[nb], a2h, b2h);
                MMA_BF16(sc2[nb], a2l, b2h);
                MMA_BF16(sc2[nb], a2h, b2l);
            }
        }

        // scale + clip (matches reference: clip(s*scale, +-100))
#pragma unroll
        for (int nb = 0; nb < 8; nb++)
#pragma unroll
            for (int j = 0; j < 4; j++) {
                sc1[nb][j] = fminf(fmaxf(sc1[nb][j]*0.125f, -ATTN_CLIP), ATTN_CLIP);
                sc2[nb][j] = fminf(fmaxf(sc2[nb][j]*0.125f, -ATTN_CLIP), ATTN_CLIP);
            }

        softmax_upd(sc1, m1, l1, oc1);
        softmax_upd(sc2, m2, l2, oc2);

        // ---- O += P V (P from S-accums via FA2 layout identity; 3-pass split) ----
#pragma unroll
        for (int kc = 0; kc < 4; kc++) {
            uint32_t p1h[4], p1l[4], p2h[4], p2l[4];
            p1h[0] = pk2(sc1[2*kc][0],   sc1[2*kc][1]);
            p1h[1] = pk2(sc1[2*kc][2],   sc1[2*kc][3]);
            p1h[2] = pk2(sc1[2*kc+1][0], sc1[2*kc+1][1]);
            p1h[3] = pk2(sc1[2*kc+1][2], sc1[2*kc+1][3]);
            p1l[0] = pk2lo(sc1[2*kc][0],   sc1[2*kc][1],   p1h[0]);
            p1l[1] = pk2lo(sc1[2*kc][2],   sc1[2*kc][3],   p1h[1]);
            p1l[2] = pk2lo(sc1[2*kc+1][0], sc1[2*kc+1][1], p1h[2]);
            p1l[3] = pk2lo(sc1[2*kc+1][2], sc1[2*kc+1][3], p1h[3]);
            p2h[0] = pk2(sc2[2*kc][0],   sc2[2*kc][1]);
            p2h[1] = pk2(sc2[2*kc][2],   sc2[2*kc][3]);
            p2h[2] = pk2(sc2[2*kc+1][0], sc2[2*kc+1][1]);
            p2h[3] = pk2(sc2[2*kc+1][2], sc2[2*kc+1][3]);
            p2l[0] = pk2lo(sc2[2*kc][0],   sc2[2*kc][1],   p2h[0]);
            p2l[1] = pk2lo(sc2[2*kc][2],   sc2[2*kc][3],   p2h[1]);
            p2l[2] = pk2lo(sc2[2*kc+1][0], sc2[2*kc+1][1], p2h[2]);
            p2l[3] = pk2lo(sc2[2*kc+1][2], sc2[2*kc+1][3], p2h[3]);
#pragma unroll
            for (int db = 0; db < 8; db++) {
                const int vo = (db*8 + g4)*AP + kc*16 + t4*2;
                uint32_t bvh[2], bvl[2];
                bvh[0] = *(const uint32_t*)&sb[TVH + vo];
                bvh[1] = *(const uint32_t*)&sb[TVH + vo + 8];
                bvl[0] = *(const uint32_t*)&sb[TVL + vo];
                bvl[1] = *(const uint32_t*)&sb[TVL + vo + 8];
                MMA_BF16(oc1[db], p1h, bvh);
                MMA_BF16(oc1[db], p1l, bvh);
                MMA_BF16(oc1[db], p1h, bvl);
                MMA_BF16(oc2[db], p2h, bvh);
                MMA_BF16(oc2[db], p2l, bvh);
                MMA_BF16(oc2[db], p2h, bvl);
            }
        }
    }

    // epilogue: combine streams, write fp32 (B,S,H*hd)
    const float i10 = 1.f/(l1[0]+EPSF), i11 = 1.f/(l1[1]+EPSF);
    const float i20 = 1.f/(l2[0]+EPSF), i21 = 1.f/(l2[1]+EPSF);
    const int r0 = q0 + wid*16 + g4;
    size_t ob0 = ((size_t)b*SEQ + r0)*DIM + (size_t)h*HDIM;
    size_t ob1 = ob0 + (size_t)8*DIM;
#pragma unroll
    for (int db = 0; db < 8; db++) {
        const int c = db*8 + t4*2;
        o[ob0 + c]     = oc1[db][0]*i10 - lam*(oc2[db][0]*i20);
        o[ob0 + c + 1] = oc1[db][1]*i10 - lam*(oc2[db][1]*i20);
        o[ob1 + c]     = oc1[db][2]*i11 - lam*(oc2[db][2]*i21);
        o[ob1 + c + 1] = oc1[db][3]*i11 - lam*(oc2[db][3]*i21);
    }
}

// ================= launch =================
extern "C" void kernel_launch(void* const* d_in, const int* in_sizes, int n_in,
                              void* d_out, int out_size) {
    const float* x      = (const float*)d_in[0];
    const float* w_qkv  = (const float*)d_in[1];
    const float* lq1    = (const float*)d_in[2];
    const float* lk1    = (const float*)d_in[3];
    const float* lq2    = (const float*)d_in[4];
    const float* lk2    = (const float*)d_in[5];
    const float* w_proj = (const float*)d_in[6];
    const float* b_proj = (const float*)d_in[7];
    const float* gamma1 = (const float*)d_in[8];
    const float* beta1  = (const float*)d_in[9];
    const float* gamma2 = (const float*)d_in[10];
    const float* beta2  = (const float*)d_in[11];
    const float* w1     = (const float*)d_in[12];
    const float* b1     = (const float*)d_in[13];
    const float* w2     = (const float*)d_in[14];
    const float* b2     = (const float*)d_in[15];
    float* out = (float*)d_out;

    float *p_h, *p_qkv, *p_o, *p_x2, *p_h2, *p_f;
    __nv_bfloat16 *p_ahi, *p_alo, *p_bhi, *p_blo;
    cudaGetSymbolAddress((void**)&p_h,   g_h);
    cudaGetSymbolAddress((void**)&p_qkv, g_qkv);
    cudaGetSymbolAddress((void**)&p_o,   g_o);
    cudaGetSymbolAddress((void**)&p_x2,  g_x2);
    cudaGetSymbolAddress((void**)&p_h2,  g_h2);
    cudaGetSymbolAddress((void**)&p_f,   g_f);
    cudaGetSymbolAddress((void**)&p_ahi, g_ahi);
    cudaGetSymbolAddress((void**)&p_alo, g_alo);
    cudaGetSymbolAddress((void**)&p_bhi, g_bhi);
    cudaGetSymbolAddress((void**)&p_blo, g_blo);

    cudaFuncSetAttribute(diff_attn_mma,
                         cudaFuncAttributeMaxDynamicSharedMemorySize, SMEM_ATT);
    cudaFuncSetAttribute(wmma_gemm<0>, cudaFuncAttributeMaxDynamicSharedMemorySize, SMEM_WG);
    cudaFuncSetAttribute(wmma_gemm<2>, cudaFuncAttributeMaxDynamicSharedMemorySize, SMEM_WG);
    cudaFuncSetAttribute(wmma_gemm<3>, cudaFuncAttributeMaxDynamicSharedMemorySize, SMEM_WG);

    // scalars
    reduce_sq_kernel<<<dim3(128, BATCH), 256>>>(x);
    compute_nx_kernel<<<1, 32>>>();
    compute_lam_kernel<<<1, 1>>>(lq1, lk1, lq2, lk2);

    // GRN1 -> h
    grn_kernel<<<(MTOT*DIM)/4/256, 256>>>(x, gamma1, beta1, p_h);

    // QKV GEMM: h(4096x1024) @ w_qkv(1024x5120)
    split_kernel<<<(MTOT*DIM)/4/256, 256>>>(p_h, p_ahi, p_alo);
    transpose_split_kernel<<<dim3(QKVW/32, DIM/32), dim3(32, 8)>>>(w_qkv, p_bhi, p_blo, DIM, QKVW);
    wmma_gemm<0><<<dim3(QKVW/128, MTOT/128), 256, SMEM_WG>>>(
        p_ahi, p_alo, p_bhi, p_blo, p_qkv, MTOT, QKVW, DIM, nullptr, nullptr);

    // tensor-core differential flash attention -> o (B,S,H*hd)
    diff_attn_mma<<<dim3(SEQ/64, NHEADS, BATCH), 128, SMEM_ATT>>>(p_qkv, p_o);

    // proj + bias + residual(x) -> x2
    split_kernel<<<(MTOT*DIM)/4/256, 256>>>(p_o, p_ahi, p_alo);
    transpose_split_kernel<<<dim3(DIM/32, DIM/32), dim3(32, 8)>>>(w_proj, p_bhi, p_blo, DIM, DIM);
    wmma_gemm<2><<<dim3(DIM/128, MTOT/128), 256, SMEM_WG>>>(
        p_ahi, p_alo, p_bhi, p_blo, p_x2, MTOT, DIM, DIM, b_proj, x);

    // GRN2 -> h2
    reduce_sq_kernel<<<dim3(128, BATCH), 256>>>(p_x2);
    compute_nx_kernel<<<1, 32>>>();
    grn_kernel<<<(MTOT*DIM)/4/256, 256>>>(p_x2, gamma2, beta2, p_h2);

    // FFN1: silu(h2 @ w1 + b1) -> f
    split_kernel<<<(MTOT*DIM)/4/256, 256>>>(p_h2, p_ahi, p_alo);
    transpose_split_kernel<<<dim3(MLP/32, DIM/32), dim3(32, 8)>>>(w1, p_bhi, p_blo, DIM, MLP);
    wmma_gemm<3><<<dim3(MLP/128, MTOT/128), 256, SMEM_WG>>>(
        p_ahi, p_alo, p_bhi, p_blo, p_f, MTOT, MLP, DIM, b1, nullptr);

    // FFN2: f @ w2 + b2 + residual(x2) -> out
    split_kernel<<<((size_t)MTOT*MLP)/4/256, 256>>>(p_f, p_ahi, p_alo);
    transpose_split_kernel<<<dim3(DIM/32, MLP/32), dim3(32, 8)>>>(w2, p_bhi, p_blo, MLP, DIM);
    wmma_gemm<2><<<dim3(DIM/128, MTOT/128), 256, SMEM_WG>>>(
        p_ahi, p_alo, p_bhi, p_blo, out, MTOT, DIM, MLP, b2, p_x2);
}

// round 8
// speedup vs baseline: 3.4563x; 1.3469x over previous
#include <cuda_runtime.h>
#include <cuda_bf16.h>
#include <mma.h>
#include <math.h>
#include <cstdint>

using namespace nvcuda;

#define BATCH 4
#define SEQ 1024
#define DIM 1024
#define NHEADS 16
#define HDIM 64
#define MLP 4096
#define MTOT (BATCH*SEQ)        /* 4096 */
#define QKVW (5*NHEADS*HDIM)    /* 5120 */
#define ATTN_CLIP 100.0f
#define NORM_CLIP 1000.0f
#define EPSF 1e-6f

// ================= scratch =================
__device__ float g_x2 [MTOT*DIM];                            // 16MB
__device__ __nv_bfloat16 g_ahi[(size_t)MTOT*MLP];            // A hi (h/o/h2): 32MB
__device__ __nv_bfloat16 g_alo[(size_t)MTOT*MLP];
__device__ __nv_bfloat16 g_qhi[(size_t)MTOT*QKVW];           // qkv hi, later f: 40MB
__device__ __nv_bfloat16 g_qlo[(size_t)MTOT*QKVW];
__device__ __nv_bfloat16 g_bhi[(size_t)QKVW*DIM];            // weights^T hi
__device__ __nv_bfloat16 g_blo[(size_t)QKVW*DIM];
__device__ __nv_bfloat16 g_vthi[(size_t)BATCH*NHEADS*HDIM*SEQ]; // V^T: 8MB
__device__ __nv_bfloat16 g_vtlo[(size_t)BATCH*NHEADS*HDIM*SEQ];
__device__ float g_part[BATCH*128];
__device__ float g_nx[BATCH];
__device__ float g_lam;

// ================= helpers =================
__device__ __forceinline__ uint32_t smem_u32(const void* p) {
    uint32_t a;
    asm("{ .reg .u64 t; cvta.to.shared.u64 t, %1; cvt.u32.u64 %0, t; }" : "=r"(a) : "l"(p));
    return a;
}
#define CP_ASYNC16(dst, src) \
    asm volatile("cp.async.cg.shared.global [%0], [%1], 16;" :: "r"(dst), "l"(src))
#define CP_COMMIT() asm volatile("cp.async.commit_group;" ::: "memory")
#define CP_WAIT(n)  asm volatile("cp.async.wait_group %0;" :: "n"(n) : "memory")

#define MMA_BF16(d, a, b) \
    asm volatile("mma.sync.aligned.m16n8k16.row.col.f32.bf16.bf16.f32 " \
        "{%0,%1,%2,%3}, {%4,%5,%6,%7}, {%8,%9}, {%0,%1,%2,%3};" \
        : "+f"((d)[0]), "+f"((d)[1]), "+f"((d)[2]), "+f"((d)[3]) \
        : "r"((a)[0]), "r"((a)[1]), "r"((a)[2]), "r"((a)[3]), \
          "r"((b)[0]), "r"((b)[1]))

__device__ __forceinline__ uint32_t pk2(float x, float y) {
    __nv_bfloat162 t = __floats2bfloat162_rn(x, y);
    return *(uint32_t*)&t;
}
__device__ __forceinline__ uint32_t pk2lo(float x, float y, uint32_t hipk) {
    __nv_bfloat162 hp = *(__nv_bfloat162*)&hipk;
    return pk2(x - __bfloat162float(hp.x), y - __bfloat162float(hp.y));
}

// ================= scalar kernels =================
__global__ void reduce_sq_kernel(const float* __restrict__ x) {
    const int b = blockIdx.y, blk = blockIdx.x;
    const int N = SEQ*DIM;
    const int per = N / 128;
    const float* p = x + (size_t)b*N + (size_t)blk*per;
    float s = 0.f;
    for (int i = threadIdx.x; i < per; i += 256) { float v = p[i]; s += v*v; }
    __shared__ float red[8];
    int lane = threadIdx.x & 31, w = threadIdx.x >> 5;
#pragma unroll
    for (int o = 16; o; o >>= 1) s += __shfl_down_sync(0xffffffffu, s, o);
    if (lane == 0) red[w] = s;
    __syncthreads();
    if (w == 0) {
        s = (lane < 8) ? red[lane] : 0.f;
#pragma unroll
        for (int o = 4; o; o >>= 1) s += __shfl_down_sync(0xffffffffu, s, o);
        if (lane == 0) g_part[b*128 + blk] = s;
    }
}

__global__ void compute_nx_kernel() {
    int b = threadIdx.x;
    if (b < BATCH) {
        float s = 0.f;
        for (int i = 0; i < 128; i++) s += g_part[b*128 + i];
        s = fminf(fmaxf(s, EPSF), NORM_CLIP);
        float gx = sqrtf(s);
        float nx = gx / (gx + EPSF);
        nx = fminf(fmaxf(nx, -NORM_CLIP), NORM_CLIP);
        g_nx[b] = nx;
    }
}

__global__ void compute_lam_kernel(const float* __restrict__ lq1, const float* __restrict__ lk1,
                                   const float* __restrict__ lq2, const float* __restrict__ lk2) {
    float s1 = 0.f, s2 = 0.f;
    for (int d = 0; d < HDIM; d++) { s1 += lq1[d]*lk1[d]; s2 += lq2[d]*lk2[d]; }
    s1 = fminf(fmaxf(s1, -10.f), 10.f);
    s2 = fminf(fmaxf(s2, -10.f), 10.f);
    float lam_init = 0.8f - 0.6f*expf(-0.0f);
    float lam = expf(s1) - expf(s2) + lam_init;
    g_lam = fminf(fmaxf(lam, 0.1f), 5.f);
}

// ================= GRN fused with hi/lo split =================
__global__ void grn_split_kernel(const float* __restrict__ x, const float* __restrict__ gamma,
                                 const float* __restrict__ beta,
                                 __nv_bfloat16* __restrict__ hi, __nv_bfloat16* __restrict__ lo) {
    int idx = blockIdx.x*blockDim.x + threadIdx.x;
    int e = idx * 4;
    int b = e >> 20;
    int d = e & (DIM-1);
    float nx = g_nx[b];
    float4 xv = *(const float4*)(x + e);
    float4 gv = *(const float4*)(gamma + d);
    float4 bv = *(const float4*)(beta + d);
    float r0 = gv.x*(xv.x*nx) + bv.x + xv.x;
    float r1 = gv.y*(xv.y*nx) + bv.y + xv.y;
    float r2 = gv.z*(xv.z*nx) + bv.z + xv.z;
    float r3 = gv.w*(xv.w*nx) + bv.w + xv.w;
    uint2 ph, pl;
    ph.x = pk2(r0, r1); ph.y = pk2(r2, r3);
    pl.x = pk2lo(r0, r1, ph.x); pl.y = pk2lo(r2, r3, ph.y);
    *(uint2*)(hi + e) = ph;
    *(uint2*)(lo + e) = pl;
}

// ================= weight transpose + split =================
__global__ void transpose_split_kernel(const float* __restrict__ w,
                                       __nv_bfloat16* __restrict__ thi,
                                       __nv_bfloat16* __restrict__ tlo,
                                       int K, int N) {
    __shared__ float tile[32][33];
    int n0 = blockIdx.x * 32, k0 = blockIdx.y * 32;
    int tx = threadIdx.x, ty = threadIdx.y;
#pragma unroll
    for (int i = 0; i < 4; i++)
        tile[ty + i*8][tx] = w[(size_t)(k0 + ty + i*8)*N + n0 + tx];
    __syncthreads();
#pragma unroll
    for (int i = 0; i < 4; i++) {
        float v = tile[tx][ty + i*8];
        __nv_bfloat16 h = __float2bfloat16(v);
        __nv_bfloat16 l = __float2bfloat16(v - __bfloat162float(h));
        size_t o = (size_t)(n0 + ty + i*8)*K + k0 + tx;
        thi[o] = h; tlo[o] = l;
    }
}

// ================= V transpose: qkv v-cols -> vt[bh][d][kk] =================
__global__ void vtrans_kernel(const __nv_bfloat16* __restrict__ qHi,
                              const __nv_bfloat16* __restrict__ qLo,
                              __nv_bfloat16* __restrict__ vtHi,
                              __nv_bfloat16* __restrict__ vtLo) {
    __shared__ __nv_bfloat16 th[32][33], tl[32][33];
    const int b = blockIdx.z;
    const int t0 = blockIdx.x * 32;       // token tile
    const int f0 = blockIdx.y * 32;       // feature tile within H*HDIM
    const int tx = threadIdx.x, ty = threadIdx.y;   // 32 x 8
#pragma unroll
    for (int i = 0; i < 4; i++) {
        size_t src = (size_t)(b*SEQ + t0 + ty + i*8)*QKVW + 4096 + f0 + tx;
        th[ty + i*8][tx] = qHi[src];
        tl[ty + i*8][tx] = qLo[src];
    }
    __syncthreads();
#pragma unroll
    for (int i = 0; i < 4; i++) {
        int f = f0 + ty + i*8;
        int h = f >> 6, d = f & 63;
        size_t dst = ((size_t)(b*NHEADS + h)*HDIM + d)*SEQ + t0 + tx;
        vtHi[dst] = th[tx][ty + i*8];
        vtLo[dst] = tl[tx][ty + i*8];
    }
}

// ================= wmma bf16-split GEMM =================
// EPI 2: fp32 C = acc + bias + res
// EPI 4: CHi/CLo = split(acc)
// EPI 5: CHi/CLo = split(silu(acc + bias))
#define KC 32
#define LDA 40
#define TILE_ELEMS (128*LDA)
#define BUF_ELEMS (4*TILE_ELEMS)
#define SMEM_WG (2*BUF_ELEMS*2)
#define SLD 132

template<int EPI>
__global__ __launch_bounds__(256, 2)
void wmma_gemm(const __nv_bfloat16* __restrict__ Ahi, const __nv_bfloat16* __restrict__ Alo,
               const __nv_bfloat16* __restrict__ Bhi, const __nv_bfloat16* __restrict__ Blo,
               float* __restrict__ C,
               __nv_bfloat16* __restrict__ CHi, __nv_bfloat16* __restrict__ CLo,
               int M, int N, int K,
               const float* __restrict__ bias, const float* __restrict__ res) {
    extern __shared__ char smem_raw[];
    __nv_bfloat16* sm = (__nv_bfloat16*)smem_raw;
    const uint32_t sm_addr = smem_u32(sm);

    const int tid = threadIdx.x;
    const int wid = tid >> 5;
    const int row0 = blockIdx.y * 128;
    const int col0 = blockIdx.x * 128;
    const int wr = (wid >> 1) * 32;
    const int wc = (wid & 1) * 64;

    const __nv_bfloat16* gsrc[4] = {
        Ahi + (size_t)row0*K, Alo + (size_t)row0*K,
        Bhi + (size_t)col0*K, Blo + (size_t)col0*K };

    int u_arr[8], u_row[8], u_col[8];
#pragma unroll
    for (int i = 0; i < 8; i++) {
        int idx = tid + i*256;
        u_arr[i] = idx >> 9;
        int rem = idx & 511;
        u_row[i] = rem >> 2;
        u_col[i] = (rem & 3) * 8;
    }

    auto issue_chunk = [&](int k0, int buf) {
        uint32_t dbase = sm_addr + (uint32_t)buf * (BUF_ELEMS*2);
#pragma unroll
        for (int i = 0; i < 8; i++) {
            const __nv_bfloat16* src = gsrc[u_arr[i]] + (size_t)u_row[i]*K + k0 + u_col[i];
            uint32_t dst = dbase + (uint32_t)(u_arr[i]*TILE_ELEMS + u_row[i]*LDA + u_col[i]) * 2;
            CP_ASYNC16(dst, src);
        }
        CP_COMMIT();
    };

    wmma::fragment<wmma::accumulator, 16, 16, 16, float> acc[2][4];
#pragma unroll
    for (int i = 0; i < 2; i++)
#pragma unroll
        for (int j = 0; j < 4; j++) wmma::fill_fragment(acc[i][j], 0.f);

    const int nch = K / KC;
    issue_chunk(0, 0);

    for (int ch = 0; ch < nch; ch++) {
        const int cur = ch & 1;
        if (ch + 1 < nch) { issue_chunk((ch+1)*KC, cur ^ 1); CP_WAIT(1); }
        else              { CP_WAIT(0); }
        __syncthreads();

        const __nv_bfloat16* b0 = sm + cur * BUF_ELEMS;
        const __nv_bfloat16* tAhi = b0 + 0*TILE_ELEMS + wr*LDA;
        const __nv_bfloat16* tAlo = b0 + 1*TILE_ELEMS + wr*LDA;
        const __nv_bfloat16* tBhi = b0 + 2*TILE_ELEMS + wc*LDA;
        const __nv_bfloat16* tBlo = b0 + 3*TILE_ELEMS + wc*LDA;

#pragma unroll
        for (int ks = 0; ks < 2; ks++) {
            wmma::fragment<wmma::matrix_a, 16, 16, 16, __nv_bfloat16, wmma::row_major> aH[2], aL[2];
            wmma::fragment<wmma::matrix_b, 16, 16, 16, __nv_bfloat16, wmma::col_major> bF[4];
            const int ko = ks * 16;
#pragma unroll
            for (int i = 0; i < 2; i++)
                wmma::load_matrix_sync(aH[i], tAhi + i*16*LDA + ko, LDA);
#pragma unroll
            for (int j = 0; j < 4; j++)
                wmma::load_matrix_sync(bF[j], tBhi + j*16*LDA + ko, LDA);
#pragma unroll
            for (int i = 0; i < 2; i++)
#pragma unroll
                for (int j = 0; j < 4; j++)
                    wmma::mma_sync(acc[i][j], aH[i], bF[j], acc[i][j]);
#pragma unroll
            for (int i = 0; i < 2; i++)
                wmma::load_matrix_sync(aL[i], tAlo + i*16*LDA + ko, LDA);
#pragma unroll
            for (int i = 0; i < 2; i++)
#pragma unroll
                for (int j = 0; j < 4; j++)
                    wmma::mma_sync(acc[i][j], aL[i], bF[j], acc[i][j]);
#pragma unroll
            for (int j = 0; j < 4; j++)
                wmma::load_matrix_sync(bF[j], tBlo + j*16*LDA + ko, LDA);
#pragma unroll
            for (int i = 0; i < 2; i++)
#pragma unroll
                for (int j = 0; j < 4; j++)
                    wmma::mma_sync(acc[i][j], aH[i], bF[j], acc[i][j]);
        }
        __syncthreads();
    }

    float* stage = (float*)smem_raw;
#pragma unroll
    for (int i = 0; i < 2; i++)
#pragma unroll
        for (int j = 0; j < 4; j++)
            wmma::store_matrix_sync(stage + (wr + i*16)*SLD + wc + j*16,
                                    acc[i][j], SLD, wmma::mem_row_major);
    __syncthreads();

    const int r = tid >> 1;
    const int c0 = (tid & 1) * 64;
    const int row = row0 + r;

    if (EPI == 2) {
        size_t obase = (size_t)row*N + col0 + c0;
#pragma unroll
        for (int j = 0; j < 16; j++) {
            float4 v = *(float4*)(stage + r*SLD + c0 + j*4);
            float4 w;
            float* vi = (float*)&v; float* wi = (float*)&w;
#pragma unroll
            for (int q = 0; q < 4; q++)
                wi[q] = vi[q] + bias[col0 + c0 + j*4 + q] + res[obase + j*4 + q];
            *(float4*)(C + obase + j*4) = w;
        }
    } else {
        __nv_bfloat16* dh = CHi + (size_t)row*N + col0 + c0;
        __nv_bfloat16* dl = CLo + (size_t)row*N + col0 + c0;
#pragma unroll
        for (int j = 0; j < 8; j++) {
            float t[8];
#pragma unroll
            for (int q = 0; q < 8; q++) {
                float v = stage[r*SLD + c0 + j*8 + q];
                if (EPI == 5) {
                    v += bias[col0 + c0 + j*8 + q];
                    v = v / (1.f + __expf(-v));
                }
                t[q] = v;
            }
            uint4 ph, pl;
            uint32_t* phi = (uint32_t*)&ph;
            uint32_t* pli = (uint32_t*)&pl;
#pragma unroll
            for (int q = 0; q < 4; q++) {
                phi[q] = pk2(t[2*q], t[2*q+1]);
                pli[q] = pk2lo(t[2*q], t[2*q+1], phi[q]);
            }
            *(uint4*)(dh + j*8) = ph;
            *(uint4*)(dl + j*8) = pl;
        }
    }
}

// ================= tensor-core differential flash attention =================
// inputs pre-split bf16 (qkvHi/qkvLo rows of 5120; vt[bh][d][kk]); cp.async tile loads.
#define AP 72
#define TQ1H 0
#define TQ1L 4608
#define TQ2H 9216
#define TQ2L 13824
#define TK1H 18432
#define TK1L 23040
#define TK2H 27648
#define TK2L 32256
#define TVH  36864
#define TVL  41472
#define SMEM_ATT (46080*2)

__device__ __forceinline__ void softmax_upd(float sc[8][4], float m[2], float l[2],
                                            float oc[8][4]) {
    float t0 = -1e30f, t1 = -1e30f;
#pragma unroll
    for (int nb = 0; nb < 8; nb++) {
        t0 = fmaxf(t0, fmaxf(sc[nb][0], sc[nb][1]));
        t1 = fmaxf(t1, fmaxf(sc[nb][2], sc[nb][3]));
    }
    t0 = fmaxf(t0, __shfl_xor_sync(0xffffffffu, t0, 1));
    t0 = fmaxf(t0, __shfl_xor_sync(0xffffffffu, t0, 2));
    t1 = fmaxf(t1, __shfl_xor_sync(0xffffffffu, t1, 1));
    t1 = fmaxf(t1, __shfl_xor_sync(0xffffffffu, t1, 2));
    float nm0 = fmaxf(m[0], t0), nm1 = fmaxf(m[1], t1);
    float c0 = __expf(m[0] - nm0), c1 = __expf(m[1] - nm1);
    float s0 = 0.f, s1 = 0.f;
#pragma unroll
    for (int nb = 0; nb < 8; nb++) {
        float p0 = __expf(sc[nb][0] - nm0); sc[nb][0] = p0; s0 += p0;
        float p1 = __expf(sc[nb][1] - nm0); sc[nb][1] = p1; s0 += p1;
        float p2 = __expf(sc[nb][2] - nm1); sc[nb][2] = p2; s1 += p2;
        float p3 = __expf(sc[nb][3] - nm1); sc[nb][3] = p3; s1 += p3;
    }
    s0 += __shfl_xor_sync(0xffffffffu, s0, 1);
    s0 += __shfl_xor_sync(0xffffffffu, s0, 2);
    s1 += __shfl_xor_sync(0xffffffffu, s1, 1);
    s1 += __shfl_xor_sync(0xffffffffu, s1, 2);
    l[0] = l[0]*c0 + s0;  l[1] = l[1]*c1 + s1;
#pragma unroll
    for (int db = 0; db < 8; db++) {
        oc[db][0] *= c0; oc[db][1] *= c0;
        oc[db][2] *= c1; oc[db][3] *= c1;
    }
    m[0] = nm0; m[1] = nm1;
}

__global__ __launch_bounds__(128)
void diff_attn_mma(const __nv_bfloat16* __restrict__ qHi, const __nv_bfloat16* __restrict__ qLo,
                   const __nv_bfloat16* __restrict__ vtHi, const __nv_bfloat16* __restrict__ vtLo,
                   __nv_bfloat16* __restrict__ oHi, __nv_bfloat16* __restrict__ oLo) {
    extern __shared__ __nv_bfloat16 sb[];
    const uint32_t smb = smem_u32(sb);
    const int tid = threadIdx.x;
    const int wid = tid >> 5, lane = tid & 31;
    const int g4 = lane >> 2, t4 = lane & 3;
    const int qt = blockIdx.x, h = blockIdx.y, b = blockIdx.z;
    const int q0 = qt * 64;
    const float lam = g_lam;

    auto ld_tile = [&](int tileEls, const __nv_bfloat16* src, int rowStride) {
#pragma unroll
        for (int i = 0; i < 4; i++) {
            int idx = tid + i*128;
            int r = idx >> 3, c8 = idx & 7;
            CP_ASYNC16(smb + (uint32_t)tileEls*2 + r*144 + c8*16,
                       src + (size_t)r*rowStride + c8*8);
        }
    };

    // Q tiles
    {
        const size_t qb = (size_t)(b*SEQ + q0)*QKVW + h*HDIM;
        ld_tile(TQ1H, qHi + qb,        QKVW);
        ld_tile(TQ1L, qLo + qb,        QKVW);
        ld_tile(TQ2H, qHi + qb + 1024, QKVW);
        ld_tile(TQ2L, qLo + qb + 1024, QKVW);
        CP_COMMIT();
    }

    float oc1[8][4], oc2[8][4];
#pragma unroll
    for (int i = 0; i < 8; i++)
#pragma unroll
        for (int j = 0; j < 4; j++) { oc1[i][j] = 0.f; oc2[i][j] = 0.f; }
    float m1[2] = {-1e30f, -1e30f}, l1[2] = {0.f, 0.f};
    float m2[2] = {-1e30f, -1e30f}, l2[2] = {0.f, 0.f};

    for (int kt = 0; kt < 16; kt++) {
        __syncthreads();   // previous iter's readers done before overwrite
        const int k0 = kt * 64;
        {
            const size_t kb = (size_t)(b*SEQ + k0)*QKVW + h*HDIM;
            const size_t vb = ((size_t)(b*NHEADS + h)*HDIM)*SEQ + k0;
            ld_tile(TK1H, qHi + kb + 2048, QKVW);
            ld_tile(TK1L, qLo + kb + 2048, QKVW);
            ld_tile(TK2H, qHi + kb + 3072, QKVW);
            ld_tile(TK2L, qLo + kb + 3072, QKVW);
            ld_tile(TVH,  vtHi + vb, SEQ);
            ld_tile(TVL,  vtLo + vb, SEQ);
            CP_COMMIT();
        }
        CP_WAIT(0);
        __syncthreads();

        // ---- S = Q K^T (3-pass split, both streams) ----
        float sc1[8][4], sc2[8][4];
#pragma unroll
        for (int i = 0; i < 8; i++)
#pragma unroll
            for (int j = 0; j < 4; j++) { sc1[i][j] = 0.f; sc2[i][j] = 0.f; }

#pragma unroll
        for (int dc = 0; dc < 4; dc++) {
            const int ar = wid*16 + g4;
            const int ac = dc*16 + t4*2;
            uint32_t a1h[4], a1l[4], a2h[4], a2l[4];
            a1h[0] = *(const uint32_t*)&sb[TQ1H + ar*AP + ac];
            a1h[1] = *(const uint32_t*)&sb[TQ1H + (ar+8)*AP + ac];
            a1h[2] = *(const uint32_t*)&sb[TQ1H + ar*AP + ac + 8];
            a1h[3] = *(const uint32_t*)&sb[TQ1H + (ar+8)*AP + ac + 8];
            a1l[0] = *(const uint32_t*)&sb[TQ1L + ar*AP + ac];
            a1l[1] = *(const uint32_t*)&sb[TQ1L + (ar+8)*AP + ac];
            a1l[2] = *(const uint32_t*)&sb[TQ1L + ar*AP + ac + 8];
            a1l[3] = *(const uint32_t*)&sb[TQ1L + (ar+8)*AP + ac + 8];
            a2h[0] = *(const uint32_t*)&sb[TQ2H + ar*AP + ac];
            a2h[1] = *(const uint32_t*)&sb[TQ2H + (ar+8)*AP + ac];
            a2h[2] = *(const uint32_t*)&sb[TQ2H + ar*AP + ac + 8];
            a2h[3] = *(const uint32_t*)&sb[TQ2H + (ar+8)*AP + ac + 8];
            a2l[0] = *(const uint32_t*)&sb[TQ2L + ar*AP + ac];
            a2l[1] = *(const uint32_t*)&sb[TQ2L + (ar+8)*AP + ac];
            a2l[2] = *(const uint32_t*)&sb[TQ2L + ar*AP + ac + 8];
            a2l[3] = *(const uint32_t*)&sb[TQ2L + (ar+8)*AP + ac + 8];
#pragma unroll
            for (int nb = 0; nb < 8; nb++) {
                const int bo = (nb*8 + g4)*AP + dc*16 + t4*2;
                uint32_t b1h[2], b1l[2], b2h[2], b2l[2];
                b1h[0] = *(const uint32_t*)&sb[TK1H + bo];
                b1h[1] = *(const uint32_t*)&sb[TK1H + bo + 8];
                b1l[0] = *(const uint32_t*)&sb[TK1L + bo];
                b1l[1] = *(const uint32_t*)&sb[TK1L + bo + 8];
                b2h[0] = *(const uint32_t*)&sb[TK2H + bo];
                b2h[1] = *(const uint32_t*)&sb[TK2H + bo + 8];
                b2l[0] = *(const uint32_t*)&sb[TK2L + bo];
                b2l[1] = *(const uint32_t*)&sb[TK2L + bo + 8];
                MMA_BF16(sc1[nb], a1h, b1h);
                MMA_BF16(sc1[nb], a1l, b1h);
                MMA_BF16(sc1[nb], a1h, b1l);
                MMA_BF16(sc2[nb], a2h, b2h);
                MMA_BF16(sc2[nb], a2l, b2h);
                MMA_BF16(sc2[nb], a2h, b2l);
            }
        }

#pragma unroll
        for (int nb = 0; nb < 8; nb++)
#pragma unroll
            for (int j = 0; j < 4; j++) {
                sc1[nb][j] = fminf(fmaxf(sc1[nb][j]*0.125f, -ATTN_CLIP), ATTN_CLIP);
                sc2[nb][j] = fminf(fmaxf(sc2[nb][j]*0.125f, -ATTN_CLIP), ATTN_CLIP);
            }

        softmax_upd(sc1, m1, l1, oc1);
        softmax_upd(sc2, m2, l2, oc2);

        // ---- O += P V ----
#pragma unroll
        for (int kc = 0; kc < 4; kc++) {
            uint32_t p1h[4], p1l[4], p2h[4], p2l[4];
            p1h[0] = pk2(sc1[2*kc][0],   sc1[2*kc][1]);
            p1h[1] = pk2(sc1[2*kc][2],   sc1[2*kc][3]);
            p1h[2] = pk2(sc1[2*kc+1][0], sc1[2*kc+1][1]);
            p1h[3] = pk2(sc1[2*kc+1][2], sc1[2*kc+1][3]);
            p1l[0] = pk2lo(sc1[2*kc][0],   sc1[2*kc][1],   p1h[0]);
            p1l[1] = pk2lo(sc1[2*kc][2],   sc1[2*kc][3],   p1h[1]);
            p1l[2] = pk2lo(sc1[2*kc+1][0], sc1[2*kc+1][1], p1h[2]);
            p1l[3] = pk2lo(sc1[2*kc+1][2], sc1[2*kc+1][3], p1h[3]);
            p2h[0] = pk2(sc2[2*kc][0],   sc2[2*kc][1]);
            p2h[1] = pk2(sc2[2*kc][2],   sc2[2*kc][3]);
            p2h[2] = pk2(sc2[2*kc+1][0], sc2[2*kc+1][1]);
            p2h[3] = pk2(sc2[2*kc+1][2], sc2[2*kc+1][3]);
            p2l[0] = pk2lo(sc2[2*kc][0],   sc2[2*kc][1],   p2h[0]);
            p2l[1] = pk2lo(sc2[2*kc][2],   sc2[2*kc][3],   p2h[1]);
            p2l[2] = pk2lo(sc2[2*kc+1][0], sc2[2*kc+1][1], p2h[2]);
            p2l[3] = pk2lo(sc2[2*kc+1][2], sc2[2*kc+1][3], p2h[3]);
#pragma unroll
            for (int db = 0; db < 8; db++) {
                const int vo = (db*8 + g4)*AP + kc*16 + t4*2;
                uint32_t bvh[2], bvl[2];
                bvh[0] = *(const uint32_t*)&sb[TVH + vo];
                bvh[1] = *(const uint32_t*)&sb[TVH + vo + 8];
                bvl[0] = *(const uint32_t*)&sb[TVL + vo];
                bvl[1] = *(const uint32_t*)&sb[TVL + vo + 8];
                MMA_BF16(oc1[db], p1h, bvh);
                MMA_BF16(oc1[db], p1l, bvh);
                MMA_BF16(oc1[db], p1h, bvl);
                MMA_BF16(oc2[db], p2h, bvh);
                MMA_BF16(oc2[db], p2l, bvh);
                MMA_BF16(oc2[db], p2h, bvl);
            }
        }
    }

    // epilogue: combine streams, split hi/lo for the proj GEMM
    const float i10 = 1.f/(l1[0]+EPSF), i11 = 1.f/(l1[1]+EPSF);
    const float i20 = 1.f/(l2[0]+EPSF), i21 = 1.f/(l2[1]+EPSF);
    const int r0 = q0 + wid*16 + g4;
    size_t ob0 = ((size_t)b*SEQ + r0)*DIM + (size_t)h*HDIM;
    size_t ob1 = ob0 + (size_t)8*DIM;
#pragma unroll
    for (int db = 0; db < 8; db++) {
        const int c = db*8 + t4*2;
        float v0 = oc1[db][0]*i10 - lam*(oc2[db][0]*i20);
        float v1 = oc1[db][1]*i10 - lam*(oc2[db][1]*i20);
        float v2 = oc1[db][2]*i11 - lam*(oc2[db][2]*i21);
        float v3 = oc1[db][3]*i11 - lam*(oc2[db][3]*i21);
        uint32_t h01 = pk2(v0, v1), h23 = pk2(v2, v3);
        *(uint32_t*)(oHi + ob0 + c) = h01;
        *(uint32_t*)(oLo + ob0 + c) = pk2lo(v0, v1, h01);
        *(uint32_t*)(oHi + ob1 + c) = h23;
        *(uint32_t*)(oLo + ob1 + c) = pk2lo(v2, v3, h23);
    }
}

// ================= launch =================
extern "C" void kernel_launch(void* const* d_in, const int* in_sizes, int n_in,
                              void* d_out, int out_size) {
    const float* x      = (const float*)d_in[0];
    const float* w_qkv  = (const float*)d_in[1];
    const float* lq1    = (const float*)d_in[2];
    const float* lk1    = (const float*)d_in[3];
    const float* lq2    = (const float*)d_in[4];
    const float* lk2    = (const float*)d_in[5];
    const float* w_proj = (const float*)d_in[6];
    const float* b_proj = (const float*)d_in[7];
    const float* gamma1 = (const float*)d_in[8];
    const float* beta1  = (const float*)d_in[9];
    const float* gamma2 = (const float*)d_in[10];
    const float* beta2  = (const float*)d_in[11];
    const float* w1     = (const float*)d_in[12];
    const float* b1     = (const float*)d_in[13];
    const float* w2     = (const float*)d_in[14];
    const float* b2     = (const float*)d_in[15];
    float* out = (float*)d_out;

    float *p_x2;
    __nv_bfloat16 *p_ahi, *p_alo, *p_qhi, *p_qlo, *p_bhi, *p_blo, *p_vthi, *p_vtlo;
    cudaGetSymbolAddress((void**)&p_x2,   g_x2);
    cudaGetSymbolAddress((void**)&p_ahi,  g_ahi);
    cudaGetSymbolAddress((void**)&p_alo,  g_alo);
    cudaGetSymbolAddress((void**)&p_qhi,  g_qhi);
    cudaGetSymbolAddress((void**)&p_qlo,  g_qlo);
    cudaGetSymbolAddress((void**)&p_bhi,  g_bhi);
    cudaGetSymbolAddress((void**)&p_blo,  g_blo);
    cudaGetSymbolAddress((void**)&p_vthi, g_vthi);
    cudaGetSymbolAddress((void**)&p_vtlo, g_vtlo);

    cudaFuncSetAttribute(diff_attn_mma,
                         cudaFuncAttributeMaxDynamicSharedMemorySize, SMEM_ATT);
    cudaFuncSetAttribute(wmma_gemm<2>, cudaFuncAttributeMaxDynamicSharedMemorySize, SMEM_WG);
    cudaFuncSetAttribute(wmma_gemm<4>, cudaFuncAttributeMaxDynamicSharedMemorySize, SMEM_WG);
    cudaFuncSetAttribute(wmma_gemm<5>, cudaFuncAttributeMaxDynamicSharedMemorySize, SMEM_WG);

    // scalars
    reduce_sq_kernel<<<dim3(128, BATCH), 256>>>(x);
    compute_nx_kernel<<<1, 32>>>();
    compute_lam_kernel<<<1, 1>>>(lq1, lk1, lq2, lk2);

    // GRN1 fused split -> a (hi/lo)
    grn_split_kernel<<<(MTOT*DIM)/4/256, 256>>>(x, gamma1, beta1, p_ahi, p_alo);

    // QKV GEMM -> qkv bf16 hi/lo
    transpose_split_kernel<<<dim3(QKVW/32, DIM/32), dim3(32, 8)>>>(w_qkv, p_bhi, p_blo, DIM, QKVW);
    wmma_gemm<4><<<dim3(QKVW/128, MTOT/128), 256, SMEM_WG>>>(
        p_ahi, p_alo, p_bhi, p_blo, nullptr, p_qhi, p_qlo, MTOT, QKVW, DIM, nullptr, nullptr);

    // V transpose -> vt[bh][d][kk]
    vtrans_kernel<<<dim3(SEQ/32, 32, BATCH), dim3(32, 8)>>>(p_qhi, p_qlo, p_vthi, p_vtlo);

    // attention -> o hi/lo (reuses a arrays)
    diff_attn_mma<<<dim3(SEQ/64, NHEADS, BATCH), 128, SMEM_ATT>>>(
        p_qhi, p_qlo, p_vthi, p_vtlo, p_ahi, p_alo);

    // proj + bias + residual(x) -> x2 fp32
    transpose_split_kernel<<<dim3(DIM/32, DIM/32), dim3(32, 8)>>>(w_proj, p_bhi, p_blo, DIM, DIM);
    wmma_gemm<2><<<dim3(DIM/128, MTOT/128), 256, SMEM_WG>>>(
        p_ahi, p_alo, p_bhi, p_blo, p_x2, nullptr, nullptr, MTOT, DIM, DIM, b_proj, x);

    // GRN2 fused split -> a (hi/lo)
    reduce_sq_kernel<<<dim3(128, BATCH), 256>>>(p_x2);
    compute_nx_kernel<<<1, 32>>>();
    grn_split_kernel<<<(MTOT*DIM)/4/256, 256>>>(p_x2, gamma2, beta2, p_ahi, p_alo);

    // FFN1: silu(h2 @ w1 + b1) -> f bf16 hi/lo (into q arrays)
    transpose_split_kernel<<<dim3(MLP/32, DIM/32), dim3(32, 8)>>>(w1, p_bhi, p_blo, DIM, MLP);
    wmma_gemm<5><<<dim3(MLP/128, MTOT/128), 256, SMEM_WG>>>(
        p_ahi, p_alo, p_bhi, p_blo, nullptr, p_qhi, p_qlo, MTOT, MLP, DIM, b1, nullptr);

    // FFN2: f @ w2 + b2 + residual(x2) -> out
    transpose_split_kernel<<<dim3(DIM/32, MLP/32), dim3(32, 8)>>>(w2, p_bhi, p_blo, MLP, DIM);
    wmma_gemm<2><<<dim3(DIM/128, MTOT/128), 256, SMEM_WG>>>(
        p_qhi, p_qlo, p_bhi, p_blo, out, nullptr, nullptr, MTOT, DIM, MLP, b2, p_x2);
}